// round 1
// baseline (speedup 1.0000x reference)
#include <cuda_runtime.h>
#include <math.h>

#define HEADS    16
#define DH       64
#define NSEQ     2048
#define BATCH    4
#define DIMIN    1024
#define HID      1024            // HEADS*DH
#define ROWS     (BATCH*NSEQ)    // 8192
#define QKV_COLS (3*HID)         // 3072
#define ATT_SCALE 0.125f         // 1/sqrt(64)

// ------------------------- static scratch (no allocs allowed) ---------------
__device__ float g_qkv[(size_t)ROWS * QKV_COLS];                    // 100.7 MB
__device__ float g_scores[(size_t)BATCH * HEADS * NSEQ * NSEQ];     // 1073 MB
__device__ float g_y[(size_t)ROWS * HID];                           // 33.6 MB
__device__ float g_m [BATCH * HEADS * NSEQ];                        // col max
__device__ float g_rl[BATCH * HEADS * NSEQ];                        // 1/col sumexp

// ------------------------- generic fp32 GEMM: C = A@B (+bias) ---------------
// A[M,K] row-major, B[K,N] row-major, C[M,N]. M,N multiples of 64, K of 16.
template <bool HAS_BIAS>
__global__ void gemm64(const float* __restrict__ A, const float* __restrict__ B,
                       const float* __restrict__ bias, float* __restrict__ C,
                       int M, int N, int K) {
    __shared__ float As[16][65];
    __shared__ float Bs[16][65];
    const int tx = threadIdx.x & 15;
    const int ty = threadIdx.x >> 4;
    const int bm = blockIdx.y * 64;
    const int bn = blockIdx.x * 64;

    float acc[4][4] = {};

    for (int k0 = 0; k0 < K; k0 += 16) {
#pragma unroll
        for (int r = 0; r < 4; r++) {             // A tile 64x16 -> As[k][m]
            int idx = threadIdx.x + r * 256;
            int m = idx >> 4, kk = idx & 15;
            As[kk][m] = A[(size_t)(bm + m) * K + k0 + kk];
        }
#pragma unroll
        for (int r = 0; r < 4; r++) {             // B tile 16x64 -> Bs[k][n]
            int idx = threadIdx.x + r * 256;
            int kk = idx >> 6, n = idx & 63;
            Bs[kk][n] = B[(size_t)(k0 + kk) * N + bn + n];
        }
        __syncthreads();
#pragma unroll
        for (int kk = 0; kk < 16; kk++) {
            float a[4], b[4];
#pragma unroll
            for (int i = 0; i < 4; i++) a[i] = As[kk][ty * 4 + i];
#pragma unroll
            for (int j = 0; j < 4; j++) b[j] = Bs[kk][tx * 4 + j];
#pragma unroll
            for (int i = 0; i < 4; i++)
#pragma unroll
                for (int j = 0; j < 4; j++)
                    acc[i][j] = fmaf(a[i], b[j], acc[i][j]);
        }
        __syncthreads();
    }

#pragma unroll
    for (int i = 0; i < 4; i++) {
        int m = bm + ty * 4 + i;
#pragma unroll
        for (int j = 0; j < 4; j++) {
            int n = bn + tx * 4 + j;
            float v = acc[i][j];
            if (HAS_BIAS) v += bias[n];
            C[(size_t)m * N + n] = v;
        }
    }
}

// ------------------------- S[bh][i][j] = scale * q_i . k_j ------------------
__global__ void scores_kernel() {
    const int bh = blockIdx.z;
    const int b  = bh >> 4, h = bh & 15;
    const int i0 = blockIdx.y * 64;
    const int j0 = blockIdx.x * 64;

    __shared__ float Qs[64][65];   // [d][i]
    __shared__ float Ks[64][65];   // [d][j]

    const float* Qbase = g_qkv + (size_t)(b * NSEQ) * QKV_COLS + h * DH;
    const float* Kbase = Qbase + HID;

    const int tx = threadIdx.x & 15;
    const int ty = threadIdx.x >> 4;

#pragma unroll
    for (int r = 0; r < 16; r++) {
        int idx = threadIdx.x + r * 256;
        int d = idx & 63, i = idx >> 6;
        Qs[d][i] = Qbase[(size_t)(i0 + i) * QKV_COLS + d];
        Ks[d][i] = Kbase[(size_t)(j0 + i) * QKV_COLS + d];
    }
    __syncthreads();

    float acc[4][4] = {};
#pragma unroll 16
    for (int d = 0; d < 64; d++) {
        float q[4], k[4];
#pragma unroll
        for (int i = 0; i < 4; i++) q[i] = Qs[d][ty * 4 + i];
#pragma unroll
        for (int j = 0; j < 4; j++) k[j] = Ks[d][tx * 4 + j];
#pragma unroll
        for (int i = 0; i < 4; i++)
#pragma unroll
            for (int j = 0; j < 4; j++)
                acc[i][j] = fmaf(q[i], k[j], acc[i][j]);
    }

    float* S = g_scores + (size_t)bh * NSEQ * NSEQ;
#pragma unroll
    for (int i = 0; i < 4; i++)
#pragma unroll
        for (int j = 0; j < 4; j++)
            S[(size_t)(i0 + ty * 4 + i) * NSEQ + j0 + tx * 4 + j] =
                acc[i][j] * ATT_SCALE;
}

// --------- per-column (over i) online max / sum-exp:  m_j, 1/l_j ------------
__global__ void stats_kernel() {
    const int bh = blockIdx.y;
    const int j  = blockIdx.x * 64 + threadIdx.x;  // blockDim = (64,4)
    const int ty = threadIdx.y;
    const float* S = g_scores + (size_t)bh * NSEQ * NSEQ;

    float m = -1e30f, l = 0.0f;
    for (int i = ty; i < NSEQ; i += 4) {
        float s = S[(size_t)i * NSEQ + j];
        float mn = fmaxf(m, s);
        l = l * __expf(m - mn) + __expf(s - mn);
        m = mn;
    }

    __shared__ float sm[4][64];
    __shared__ float sl[4][64];
    sm[ty][threadIdx.x] = m;
    sl[ty][threadIdx.x] = l;
    __syncthreads();

    if (ty == 0) {
#pragma unroll
        for (int r = 1; r < 4; r++) {
            float m2 = sm[r][threadIdx.x], l2 = sl[r][threadIdx.x];
            float mn = fmaxf(m, m2);
            l = l * __expf(m - mn) + l2 * __expf(m2 - mn);
            m = mn;
        }
        g_m [bh * NSEQ + j] = m;
        g_rl[bh * NSEQ + j] = 1.0f / l;
    }
}

// --------- Y[b,i,h*64+d] = sum_j exp(S[i,j]-m_j)/l_j * V[j,d] ---------------
__global__ void av_kernel() {
    const int bh = blockIdx.y;
    const int b  = bh >> 4, h = bh & 15;
    const int i0 = blockIdx.x * 64;

    __shared__ float Ps[64][65];   // [j][i]
    __shared__ float Vs[64][65];   // [j][d]

    const float* S     = g_scores + (size_t)bh * NSEQ * NSEQ;
    const float* Vbase = g_qkv + (size_t)(b * NSEQ) * QKV_COLS + 2 * HID + h * DH;
    const float* mcol  = g_m  + bh * NSEQ;
    const float* rlcol = g_rl + bh * NSEQ;

    const int tx = threadIdx.x & 15;
    const int ty = threadIdx.x >> 4;

    float acc[4][4] = {};

    for (int j0 = 0; j0 < NSEQ; j0 += 64) {
        const int jme = threadIdx.x & 63;          // j-lane for all 16 loads
        const float mj  = mcol [j0 + jme];
        const float rlj = rlcol[j0 + jme];
#pragma unroll
        for (int r = 0; r < 16; r++) {
            int idx = threadIdx.x + r * 256;
            int jp = idx & 63, ip = idx >> 6;      // jp == jme
            float s = S[(size_t)(i0 + ip) * NSEQ + j0 + jp];
            Ps[jp][ip] = __expf(s - mj) * rlj;
        }
#pragma unroll
        for (int r = 0; r < 16; r++) {
            int idx = threadIdx.x + r * 256;
            int d = idx & 63, jp = idx >> 6;
            Vs[jp][d] = Vbase[(size_t)(j0 + jp) * QKV_COLS + d];
        }
        __syncthreads();
#pragma unroll 16
        for (int jj = 0; jj < 64; jj++) {
            float p[4], v[4];
#pragma unroll
            for (int i = 0; i < 4; i++) p[i] = Ps[jj][ty * 4 + i];
#pragma unroll
            for (int j = 0; j < 4; j++) v[j] = Vs[jj][tx * 4 + j];
#pragma unroll
            for (int i = 0; i < 4; i++)
#pragma unroll
                for (int j = 0; j < 4; j++)
                    acc[i][j] = fmaf(p[i], v[j], acc[i][j]);
        }
        __syncthreads();
    }

#pragma unroll
    for (int i = 0; i < 4; i++) {
        int row = b * NSEQ + i0 + ty * 4 + i;
#pragma unroll
        for (int j = 0; j < 4; j++)
            g_y[(size_t)row * HID + h * DH + tx * 4 + j] = acc[i][j];
    }
}

// ----------------------------------------------------------------------------
extern "C" void kernel_launch(void* const* d_in, const int* in_sizes, int n_in,
                              void* d_out, int out_size) {
    const float* x     = (const float*)d_in[0];
    const float* w_qkv = (const float*)d_in[1];
    const float* w_out = (const float*)d_in[2];
    const float* b_out = (const float*)d_in[3];
    float* out = (float*)d_out;

    void *p_qkv, *p_y;
    cudaGetSymbolAddress(&p_qkv, g_qkv);
    cudaGetSymbolAddress(&p_y,   g_y);

    dim3 blk256(256);

    // 1. QKV projection: [8192,1024] @ [1024,3072]
    gemm64<false><<<dim3(QKV_COLS / 64, ROWS / 64), blk256>>>(
        x, w_qkv, nullptr, (float*)p_qkv, ROWS, QKV_COLS, DIMIN);

    // 2. S = scale * Q K^T per (b,h)
    scores_kernel<<<dim3(NSEQ / 64, NSEQ / 64, BATCH * HEADS), blk256>>>();

    // 3. column (query-axis) softmax stats
    stats_kernel<<<dim3(NSEQ / 64, BATCH * HEADS), dim3(64, 4)>>>();

    // 4. Y = softmax_cols(S) @ V, written as [b,n,hid]
    av_kernel<<<dim3(NSEQ / 64, BATCH * HEADS), blk256>>>();

    // 5. out = Y @ w_out + b_out
    gemm64<true><<<dim3(HID / 64, ROWS / 64), blk256>>>(
        (const float*)p_y, w_out, b_out, out, ROWS, HID, DIMIN);
}

// round 2
// speedup vs baseline: 1.5180x; 1.5180x over previous
#include <cuda_runtime.h>
#include <math.h>

#define HEADS    16
#define DH       64
#define NSEQ     2048
#define BATCH    4
#define DIMIN    1024
#define HID      1024
#define ROWS     (BATCH*NSEQ)     // 8192
#define QKV_COLS (3*HID)          // 3072
#define BH       (BATCH*HEADS)    // 64
#define ATT_SCALE 0.125f

// ---------------- static scratch ----------------
__device__ float g_qkv[(size_t)ROWS * QKV_COLS];                 // 100.7 MB
__device__ float g_scores[(size_t)BH * NSEQ * NSEQ];             // 1073 MB (holds exp(s))
__device__ float g_y[(size_t)ROWS * HID];                        // 33.6 MB
__device__ float g_rl[BH * NSEQ];                                // 1/colsum

// =====================================================================
// GEMM: C[M,N] = A[M,K] @ B[K,N] (+bias). 128x128 tile, 8x8 micro,
// double-buffered smem, 256 threads. M,N %128==0, K %16==0.
// =====================================================================
template <bool HAS_BIAS>
__global__ __launch_bounds__(256) void gemm128(
    const float* __restrict__ A, const float* __restrict__ B,
    const float* __restrict__ bias, float* __restrict__ C,
    int M, int N, int K)
{
    __shared__ float As[2][16][128];
    __shared__ float Bs[2][16][128];

    const int t  = threadIdx.x;
    const int tx = t & 15;
    const int ty = t >> 4;
    const int bm = blockIdx.y * 128;
    const int bn = blockIdx.x * 128;

    // global-load mapping
    const int arow = t >> 1;            // 0..127
    const int ak   = (t & 1) * 8;       // 0 or 8
    const int brow = t >> 4;            // 0..15
    const int bcol = (t & 15) * 8;      // 0..120

    const float* Ag = A + (size_t)(bm + arow) * K + ak;
    const float* Bg = B + (size_t)brow * N + bn + bcol;

    float4 la0, la1, lb0, lb1;

    // prologue: tile 0
    la0 = *(const float4*)(Ag + 0);
    la1 = *(const float4*)(Ag + 4);
    lb0 = *(const float4*)(Bg + 0);
    lb1 = *(const float4*)(Bg + 4);
    {
        As[0][ak+0][arow] = la0.x; As[0][ak+1][arow] = la0.y;
        As[0][ak+2][arow] = la0.z; As[0][ak+3][arow] = la0.w;
        As[0][ak+4][arow] = la1.x; As[0][ak+5][arow] = la1.y;
        As[0][ak+6][arow] = la1.z; As[0][ak+7][arow] = la1.w;
        *(float4*)&Bs[0][brow][bcol]     = lb0;
        *(float4*)&Bs[0][brow][bcol + 4] = lb1;
    }
    __syncthreads();

    float acc[8][8] = {};
    const int NT = K / 16;
    int cur = 0;

    for (int kt = 0; kt < NT; kt++) {
        if (kt + 1 < NT) {
            const float* Ag2 = Ag + (size_t)(kt + 1) * 16;
            const float* Bg2 = Bg + (size_t)(kt + 1) * 16 * N;
            la0 = *(const float4*)(Ag2 + 0);
            la1 = *(const float4*)(Ag2 + 4);
            lb0 = *(const float4*)(Bg2 + 0);
            lb1 = *(const float4*)(Bg2 + 4);
        }
#pragma unroll
        for (int kk = 0; kk < 16; kk++) {
            float4 a0 = *(const float4*)&As[cur][kk][ty * 4];
            float4 a1 = *(const float4*)&As[cur][kk][64 + ty * 4];
            float4 b0 = *(const float4*)&Bs[cur][kk][tx * 4];
            float4 b1 = *(const float4*)&Bs[cur][kk][64 + tx * 4];
            const float av[8] = {a0.x,a0.y,a0.z,a0.w,a1.x,a1.y,a1.z,a1.w};
            const float bv[8] = {b0.x,b0.y,b0.z,b0.w,b1.x,b1.y,b1.z,b1.w};
#pragma unroll
            for (int i = 0; i < 8; i++)
#pragma unroll
                for (int j = 0; j < 8; j++)
                    acc[i][j] = fmaf(av[i], bv[j], acc[i][j]);
        }
        if (kt + 1 < NT) {
            int nxt = cur ^ 1;
            As[nxt][ak+0][arow] = la0.x; As[nxt][ak+1][arow] = la0.y;
            As[nxt][ak+2][arow] = la0.z; As[nxt][ak+3][arow] = la0.w;
            As[nxt][ak+4][arow] = la1.x; As[nxt][ak+5][arow] = la1.y;
            As[nxt][ak+6][arow] = la1.z; As[nxt][ak+7][arow] = la1.w;
            *(float4*)&Bs[nxt][brow][bcol]     = lb0;
            *(float4*)&Bs[nxt][brow][bcol + 4] = lb1;
            __syncthreads();
            cur = nxt;
        }
    }

    // epilogue
    float4 bias0, bias1;
    if (HAS_BIAS) {
        bias0 = *(const float4*)(bias + bn + tx * 4);
        bias1 = *(const float4*)(bias + bn + 64 + tx * 4);
    }
#pragma unroll
    for (int i = 0; i < 8; i++) {
        int row = bm + ((i < 4) ? (ty * 4 + i) : (64 + ty * 4 + i - 4));
        float4 c0, c1;
        c0.x = acc[i][0]; c0.y = acc[i][1]; c0.z = acc[i][2]; c0.w = acc[i][3];
        c1.x = acc[i][4]; c1.y = acc[i][5]; c1.z = acc[i][6]; c1.w = acc[i][7];
        if (HAS_BIAS) {
            c0.x += bias0.x; c0.y += bias0.y; c0.z += bias0.z; c0.w += bias0.w;
            c1.x += bias1.x; c1.y += bias1.y; c1.z += bias1.z; c1.w += bias1.w;
        }
        *(float4*)(C + (size_t)row * N + bn + tx * 4)      = c0;
        *(float4*)(C + (size_t)row * N + bn + 64 + tx * 4) = c1;
    }
}

// =====================================================================
// scores: P[bh][i][j] = exp(scale * q_i . k_j).  128x128 tile, d in 2x32.
// =====================================================================
__global__ __launch_bounds__(256) void scores_kernel() {
    __shared__ float Qs[32][128];
    __shared__ float Ks[32][128];

    const int bh = blockIdx.z;
    const int b  = bh >> 4, h = bh & 15;
    const int i0 = blockIdx.y * 128;
    const int j0 = blockIdx.x * 128;

    const float* Qbase = g_qkv + (size_t)(b * NSEQ) * QKV_COLS + h * DH;
    const float* Kbase = Qbase + HID;

    const int t  = threadIdx.x;
    const int tx = t & 15;
    const int ty = t >> 4;
    const int lrow  = t >> 1;          // 0..127
    const int ldoff = (t & 1) * 16;    // 0 or 16

    float acc[8][8] = {};

    for (int d0 = 0; d0 < DH; d0 += 32) {
        // load Q tile [128 i][32 d] transposed, K tile [128 j][32 d]
        const float* Qr = Qbase + (size_t)(i0 + lrow) * QKV_COLS + d0 + ldoff;
        const float* Kr = Kbase + (size_t)(j0 + lrow) * QKV_COLS + d0 + ldoff;
#pragma unroll
        for (int q = 0; q < 4; q++) {
            float4 v = *(const float4*)(Qr + q * 4);
            Qs[ldoff + q*4 + 0][lrow] = v.x;
            Qs[ldoff + q*4 + 1][lrow] = v.y;
            Qs[ldoff + q*4 + 2][lrow] = v.z;
            Qs[ldoff + q*4 + 3][lrow] = v.w;
            float4 w = *(const float4*)(Kr + q * 4);
            Ks[ldoff + q*4 + 0][lrow] = w.x;
            Ks[ldoff + q*4 + 1][lrow] = w.y;
            Ks[ldoff + q*4 + 2][lrow] = w.z;
            Ks[ldoff + q*4 + 3][lrow] = w.w;
        }
        __syncthreads();
#pragma unroll
        for (int dd = 0; dd < 32; dd++) {
            float4 a0 = *(const float4*)&Qs[dd][ty * 4];
            float4 a1 = *(const float4*)&Qs[dd][64 + ty * 4];
            float4 b0 = *(const float4*)&Ks[dd][tx * 4];
            float4 b1 = *(const float4*)&Ks[dd][64 + tx * 4];
            const float qv[8] = {a0.x,a0.y,a0.z,a0.w,a1.x,a1.y,a1.z,a1.w};
            const float kv[8] = {b0.x,b0.y,b0.z,b0.w,b1.x,b1.y,b1.z,b1.w};
#pragma unroll
            for (int i = 0; i < 8; i++)
#pragma unroll
                for (int j = 0; j < 8; j++)
                    acc[i][j] = fmaf(qv[i], kv[j], acc[i][j]);
        }
        __syncthreads();
    }

    float* S = g_scores + (size_t)bh * NSEQ * NSEQ;
#pragma unroll
    for (int i = 0; i < 8; i++) {
        int row = i0 + ((i < 4) ? (ty * 4 + i) : (64 + ty * 4 + i - 4));
        float4 c0, c1;
        c0.x = __expf(acc[i][0] * ATT_SCALE);
        c0.y = __expf(acc[i][1] * ATT_SCALE);
        c0.z = __expf(acc[i][2] * ATT_SCALE);
        c0.w = __expf(acc[i][3] * ATT_SCALE);
        c1.x = __expf(acc[i][4] * ATT_SCALE);
        c1.y = __expf(acc[i][5] * ATT_SCALE);
        c1.z = __expf(acc[i][6] * ATT_SCALE);
        c1.w = __expf(acc[i][7] * ATT_SCALE);
        *(float4*)(S + (size_t)row * NSEQ + j0 + tx * 4)      = c0;
        *(float4*)(S + (size_t)row * NSEQ + j0 + 64 + tx * 4) = c1;
    }
}

// =====================================================================
// colsum: rl[bh][j] = 1 / sum_i P[i][j]
// =====================================================================
__global__ void colsum_kernel() {
    const int bh = blockIdx.y;
    const int j  = blockIdx.x * 64 + threadIdx.x;   // blockDim (64,8)
    const int ty = threadIdx.y;
    const float* S = g_scores + (size_t)bh * NSEQ * NSEQ;

    float s = 0.0f;
#pragma unroll 4
    for (int i = ty; i < NSEQ; i += 8)
        s += S[(size_t)i * NSEQ + j];

    __shared__ float sm[8][64];
    sm[ty][threadIdx.x] = s;
    __syncthreads();
    if (ty == 0) {
        float tot = s;
#pragma unroll
        for (int r = 1; r < 8; r++) tot += sm[r][threadIdx.x];
        g_rl[bh * NSEQ + j] = 1.0f / tot;
    }
}

// =====================================================================
// av: Y[b,i,h*64+d] = sum_j P[i,j] * (rl_j * V[j,d]).  Tile 128i x 64d,
// j in chunks of 32.
// =====================================================================
__global__ __launch_bounds__(256) void av_kernel() {
    __shared__ float Ps[32][128];
    __shared__ float Vs[32][68];

    const int bh = blockIdx.y;
    const int b  = bh >> 4, h = bh & 15;
    const int i0 = blockIdx.x * 128;

    const float* S     = g_scores + (size_t)bh * NSEQ * NSEQ;
    const float* Vbase = g_qkv + (size_t)(b * NSEQ) * QKV_COLS + 2 * HID + h * DH;
    const float* rl    = g_rl + bh * NSEQ;

    const int t  = threadIdx.x;
    const int tx = t & 15;
    const int ty = t >> 4;
    const int prow  = t >> 1;          // 0..127  (i for P load)
    const int pjoff = (t & 1) * 16;    // 0/16    (j offset for P load)
    const int vrow  = t >> 3;          // 0..31   (j for V load)
    const int vdoff = (t & 7) * 8;     // 0..56   (d offset for V load)

    float acc[8][4] = {};

    for (int j0 = 0; j0 < NSEQ; j0 += 32) {
        // P tile [128 i][32 j] -> Ps[j][i] (transposed)
        const float* Pr = S + (size_t)(i0 + prow) * NSEQ + j0 + pjoff;
#pragma unroll
        for (int q = 0; q < 4; q++) {
            float4 v = *(const float4*)(Pr + q * 4);
            Ps[pjoff + q*4 + 0][prow] = v.x;
            Ps[pjoff + q*4 + 1][prow] = v.y;
            Ps[pjoff + q*4 + 2][prow] = v.z;
            Ps[pjoff + q*4 + 3][prow] = v.w;
        }
        // V tile [32 j][64 d], scaled by rl[j]
        {
            const float rlv = rl[j0 + vrow];
            const float* Vr = Vbase + (size_t)(j0 + vrow) * QKV_COLS + vdoff;
            float4 v0 = *(const float4*)(Vr + 0);
            float4 v1 = *(const float4*)(Vr + 4);
            v0.x *= rlv; v0.y *= rlv; v0.z *= rlv; v0.w *= rlv;
            v1.x *= rlv; v1.y *= rlv; v1.z *= rlv; v1.w *= rlv;
            *(float4*)&Vs[vrow][vdoff]     = v0;
            *(float4*)&Vs[vrow][vdoff + 4] = v1;
        }
        __syncthreads();
#pragma unroll
        for (int jj = 0; jj < 32; jj++) {
            float4 p0 = *(const float4*)&Ps[jj][ty * 4];
            float4 p1 = *(const float4*)&Ps[jj][64 + ty * 4];
            float4 vv = *(const float4*)&Vs[jj][tx * 4];
            const float pv[8] = {p0.x,p0.y,p0.z,p0.w,p1.x,p1.y,p1.z,p1.w};
            const float vb[4] = {vv.x,vv.y,vv.z,vv.w};
#pragma unroll
            for (int i = 0; i < 8; i++)
#pragma unroll
                for (int j = 0; j < 4; j++)
                    acc[i][j] = fmaf(pv[i], vb[j], acc[i][j]);
        }
        __syncthreads();
    }

#pragma unroll
    for (int i = 0; i < 8; i++) {
        int row = b * NSEQ + i0 + ((i < 4) ? (ty * 4 + i) : (64 + ty * 4 + i - 4));
        float4 c;
        c.x = acc[i][0]; c.y = acc[i][1]; c.z = acc[i][2]; c.w = acc[i][3];
        *(float4*)(g_y + (size_t)row * HID + h * DH + tx * 4) = c;
    }
}

// ---------------------------------------------------------------------
extern "C" void kernel_launch(void* const* d_in, const int* in_sizes, int n_in,
                              void* d_out, int out_size) {
    const float* x     = (const float*)d_in[0];
    const float* w_qkv = (const float*)d_in[1];
    const float* w_out = (const float*)d_in[2];
    const float* b_out = (const float*)d_in[3];
    float* out = (float*)d_out;

    void *p_qkv, *p_y;
    cudaGetSymbolAddress(&p_qkv, g_qkv);
    cudaGetSymbolAddress(&p_y,   g_y);

    // 1. QKV projection
    gemm128<false><<<dim3(QKV_COLS / 128, ROWS / 128), 256>>>(
        x, w_qkv, nullptr, (float*)p_qkv, ROWS, QKV_COLS, DIMIN);

    // 2. P = exp(scale * Q K^T)
    scores_kernel<<<dim3(NSEQ / 128, NSEQ / 128, BH), 256>>>();

    // 3. column sums (query-axis softmax denominator)
    colsum_kernel<<<dim3(NSEQ / 64, BH), dim3(64, 8)>>>();

    // 4. Y = P * diag(rl) @ V
    av_kernel<<<dim3(NSEQ / 128, BH), 256>>>();

    // 5. out = Y @ w_out + b_out
    gemm128<true><<<dim3(HID / 128, ROWS / 128), 256>>>(
        (const float*)p_y, w_out, b_out, out, ROWS, HID, DIMIN);
}

// round 5
// speedup vs baseline: 2.3100x; 1.5217x over previous
#include <cuda_runtime.h>
#include <cuda_bf16.h>
#include <math.h>
#include <stdint.h>

#define HEADS    16
#define DH       64
#define NSEQ     2048
#define BATCH    4
#define DIMIN    1024
#define HID      1024
#define ROWS     (BATCH*NSEQ)     // 8192
#define QKV_COLS (3*HID)          // 3072
#define BH       (BATCH*HEADS)    // 64
#define ATT_SCALE 0.125f
#define LDK      40               // padded k-stride (bf16 elems)

// ---------------- static scratch ----------------
__device__ float g_qkv[(size_t)ROWS * QKV_COLS];            // fp32 QKV (V used by av)
__device__ float g_rl[BH * NSEQ];                           // 1/colsum
__device__ __nv_bfloat16 g_Ph [(size_t)BH * NSEQ * NSEQ];   // P hi (537MB)
__device__ __nv_bfloat16 g_Pl [(size_t)BH * NSEQ * NSEQ];   // P lo (537MB)
__device__ __nv_bfloat16 g_xh [(size_t)ROWS * DIMIN];
__device__ __nv_bfloat16 g_xl [(size_t)ROWS * DIMIN];
__device__ __nv_bfloat16 g_qkvh[(size_t)ROWS * QKV_COLS];
__device__ __nv_bfloat16 g_qkvl[(size_t)ROWS * QKV_COLS];
__device__ __nv_bfloat16 g_wqh[(size_t)QKV_COLS * DIMIN];   // w_qkv^T hi  [N,K]
__device__ __nv_bfloat16 g_wql[(size_t)QKV_COLS * DIMIN];
__device__ __nv_bfloat16 g_woh[(size_t)DIMIN * HID];        // w_out^T hi  [N,K]
__device__ __nv_bfloat16 g_wol[(size_t)DIMIN * HID];
__device__ __nv_bfloat16 g_yh [(size_t)ROWS * HID];
__device__ __nv_bfloat16 g_yl [(size_t)ROWS * HID];

// ---------------- helpers ----------------
__device__ __forceinline__ uint32_t smem_u32(const void* p) {
    uint32_t a;
    asm("{ .reg .u64 t; cvta.to.shared.u64 t, %1; cvt.u32.u64 %0, t; }"
        : "=r"(a) : "l"(p));
    return a;
}
__device__ __forceinline__ void cp_async16(uint32_t s, const void* g) {
    asm volatile("cp.async.cg.shared.global [%0], [%1], 16;" :: "r"(s), "l"(g));
}
#define CP_COMMIT() asm volatile("cp.async.commit_group;" ::: "memory")
template <int N>
__device__ __forceinline__ void cp_wait() {
    asm volatile("cp.async.wait_group %0;" :: "n"(N) : "memory");
}

// mma.sync m16n8k16 bf16: D += A*B  (acc fp32)
__device__ __forceinline__ void mma_bf(float* c, const uint32_t* a,
                                       uint32_t b0, uint32_t b1) {
    asm volatile(
        "mma.sync.aligned.m16n8k16.row.col.f32.bf16.bf16.f32 "
        "{%0,%1,%2,%3}, {%4,%5,%6,%7}, {%8,%9}, {%0,%1,%2,%3};\n"
        : "+f"(c[0]), "+f"(c[1]), "+f"(c[2]), "+f"(c[3])
        : "r"(a[0]), "r"(a[1]), "r"(a[2]), "r"(a[3]), "r"(b0), "r"(b1));
}

// A fragment (row-major 16x16 tile at rows r0.., k offset ks)
__device__ __forceinline__ void ldA(uint32_t* a, const char* M, int r0, int ks,
                                    int g, int ti) {
    a[0] = *(const uint32_t*)(M + ((r0 + g    ) * LDK + ks + ti * 2    ) * 2);
    a[1] = *(const uint32_t*)(M + ((r0 + g + 8) * LDK + ks + ti * 2    ) * 2);
    a[2] = *(const uint32_t*)(M + ((r0 + g    ) * LDK + ks + ti * 2 + 8) * 2);
    a[3] = *(const uint32_t*)(M + ((r0 + g + 8) * LDK + ks + ti * 2 + 8) * 2);
}
// B fragment: storage [N,K] row-major == col-major KxN as mma wants
__device__ __forceinline__ void ldB(uint32_t& b0, uint32_t& b1, const char* M,
                                    int n0, int ks, int g, int ti) {
    b0 = *(const uint32_t*)(M + ((n0 + g) * LDK + ks + ti * 2    ) * 2);
    b1 = *(const uint32_t*)(M + ((n0 + g) * LDK + ks + ti * 2 + 8) * 2);
}

__device__ __forceinline__ void split2(float a, float b,
                                       __nv_bfloat162& hp, __nv_bfloat162& lp) {
    __nv_bfloat16 ha = __float2bfloat16(a), hb = __float2bfloat16(b);
    hp.x = ha; hp.y = hb;
    lp.x = __float2bfloat16(a - __bfloat162float(ha));
    lp.y = __float2bfloat16(b - __bfloat162float(hb));
}

// stage layout (bytes): Ah 0 | Al 10240 | Bh 20480 | Bl 30720 ; stage size 40960
#define STG 40960
#define DSMEM (2*STG)

__device__ __forceinline__ void stage_load(char* sb,
    const __nv_bfloat16* Ah, const __nv_bfloat16* Al, int sA,
    const __nv_bfloat16* Bh, const __nv_bfloat16* Bl, int sB,
    int k0, int tid)
{
    uint32_t sbase = smem_u32(sb);
#pragma unroll
    for (int r = 0; r < 2; r++) {
        int sid = tid + (r << 8);
        int row = sid >> 2, seg = sid & 3;
        uint32_t so = sbase + (uint32_t)(row * (LDK * 2) + seg * 16);
        size_t oa = (size_t)row * sA + k0 + seg * 8;
        size_t ob = (size_t)row * sB + k0 + seg * 8;
        cp_async16(so,          Ah + oa);
        cp_async16(so + 10240u, Al + oa);
        cp_async16(so + 20480u, Bh + ob);
        cp_async16(so + 30720u, Bl + ob);
    }
}

// 3-pass bf16 compute of one 32-k chunk; warp tile 32(m) x 64(n)
__device__ __forceinline__ void mma_chunk3(const char* sb, int warp_m, int warp_n,
                                           int g, int ti, float acc[2][8][4]) {
    const char* Ah = sb;
    const char* Al = sb + 10240;
    const char* Bh = sb + 20480;
    const char* Bl = sb + 30720;
#pragma unroll
    for (int ks = 0; ks < 32; ks += 16) {
        uint32_t aH[2][4], aL[2][4];
#pragma unroll
        for (int mt = 0; mt < 2; mt++) {
            int r0 = warp_m * 32 + mt * 16;
            ldA(aH[mt], Ah, r0, ks, g, ti);
            ldA(aL[mt], Al, r0, ks, g, ti);
        }
#pragma unroll
        for (int nt = 0; nt < 8; nt++) {
            int n0 = warp_n * 64 + nt * 8;
            uint32_t bh0, bh1, bl0, bl1;
            ldB(bh0, bh1, Bh, n0, ks, g, ti);
            ldB(bl0, bl1, Bl, n0, ks, g, ti);
#pragma unroll
            for (int mt = 0; mt < 2; mt++) {
                mma_bf(acc[mt][nt], aH[mt], bh0, bh1);
                mma_bf(acc[mt][nt], aH[mt], bl0, bl1);
                mma_bf(acc[mt][nt], aL[mt], bh0, bh1);
            }
        }
    }
}

// =====================================================================
// projections: C[M,N] = (Ah+Al)[M,K] @ ((Bh+Bl)[N,K])^T
// =====================================================================
template <bool HAS_BIAS, bool WRITE_SPLIT>
__global__ __launch_bounds__(256) void mma_gemm(
    const __nv_bfloat16* __restrict__ Ah, const __nv_bfloat16* __restrict__ Al,
    const __nv_bfloat16* __restrict__ Bh, const __nv_bfloat16* __restrict__ Bl,
    const float* __restrict__ bias, float* __restrict__ C,
    __nv_bfloat16* __restrict__ Ch, __nv_bfloat16* __restrict__ Cl,
    int M, int N, int K)
{
    extern __shared__ char smem[];
    const int tid = threadIdx.x, lane = tid & 31, wid = tid >> 5;
    const int warp_m = wid & 3, warp_n = wid >> 2;
    const int g = lane >> 2, ti = lane & 3;
    const int bm = blockIdx.y * 128, bn = blockIdx.x * 128;

    const __nv_bfloat16* Ah0 = Ah + (size_t)bm * K;
    const __nv_bfloat16* Al0 = Al + (size_t)bm * K;
    const __nv_bfloat16* Bh0 = Bh + (size_t)bn * K;
    const __nv_bfloat16* Bl0 = Bl + (size_t)bn * K;

    float acc[2][8][4] = {};
    const int NT = K >> 5;

    stage_load(smem, Ah0, Al0, K, Bh0, Bl0, K, 0, tid);
    CP_COMMIT();
    for (int kt = 0; kt < NT; kt++) {
        if (kt + 1 < NT) {
            stage_load(smem + ((kt + 1) & 1) * STG, Ah0, Al0, K, Bh0, Bl0, K,
                       (kt + 1) << 5, tid);
            CP_COMMIT();
            cp_wait<1>();
        } else {
            cp_wait<0>();
        }
        __syncthreads();
        mma_chunk3(smem + (kt & 1) * STG, warp_m, warp_n, g, ti, acc);
        __syncthreads();
    }

#pragma unroll
    for (int mt = 0; mt < 2; mt++) {
        int r0 = bm + warp_m * 32 + mt * 16 + g;
#pragma unroll
        for (int nt = 0; nt < 8; nt++) {
            int col = bn + warp_n * 64 + nt * 8 + ti * 2;
            float v0 = acc[mt][nt][0], v1 = acc[mt][nt][1];
            float v2 = acc[mt][nt][2], v3 = acc[mt][nt][3];
            if (HAS_BIAS) {
                float2 bb = *(const float2*)(bias + col);
                v0 += bb.x; v1 += bb.y; v2 += bb.x; v3 += bb.y;
            }
            *(float2*)(C + (size_t)r0 * N + col)       = make_float2(v0, v1);
            *(float2*)(C + (size_t)(r0 + 8) * N + col) = make_float2(v2, v3);
            if (WRITE_SPLIT) {
                __nv_bfloat162 hp, lp;
                split2(v0, v1, hp, lp);
                *(__nv_bfloat162*)(Ch + (size_t)r0 * N + col) = hp;
                *(__nv_bfloat162*)(Cl + (size_t)r0 * N + col) = lp;
                split2(v2, v3, hp, lp);
                *(__nv_bfloat162*)(Ch + (size_t)(r0 + 8) * N + col) = hp;
                *(__nv_bfloat162*)(Cl + (size_t)(r0 + 8) * N + col) = lp;
            }
        }
    }
}

// =====================================================================
// scores: P = exp(scale * q.k) stored as bf16 hi/lo pair (exact to 2^-18)
// =====================================================================
__global__ __launch_bounds__(256) void scores_mma() {
    extern __shared__ char smem[];
    const int tid = threadIdx.x, lane = tid & 31, wid = tid >> 5;
    const int warp_m = wid & 3, warp_n = wid >> 2;
    const int g = lane >> 2, ti = lane & 3;

    const int bh = blockIdx.z;
    const int b = bh >> 4, h = bh & 15;
    const int i0 = blockIdx.y * 128;
    const int j0 = blockIdx.x * 128;

    const size_t qoff = (size_t)(b * NSEQ) * QKV_COLS + h * DH;
    const __nv_bfloat16* Qh = g_qkvh + qoff + (size_t)i0 * QKV_COLS;
    const __nv_bfloat16* Ql = g_qkvl + qoff + (size_t)i0 * QKV_COLS;
    const __nv_bfloat16* Kh = g_qkvh + qoff + HID + (size_t)j0 * QKV_COLS;
    const __nv_bfloat16* Kl = g_qkvl + qoff + HID + (size_t)j0 * QKV_COLS;

    float acc[2][8][4] = {};

    stage_load(smem, Qh, Ql, QKV_COLS, Kh, Kl, QKV_COLS, 0, tid);
    CP_COMMIT();
#pragma unroll
    for (int kt = 0; kt < 2; kt++) {
        if (kt == 0) {
            stage_load(smem + STG, Qh, Ql, QKV_COLS, Kh, Kl, QKV_COLS, 32, tid);
            CP_COMMIT();
            cp_wait<1>();
        } else {
            cp_wait<0>();
        }
        __syncthreads();
        mma_chunk3(smem + kt * STG, warp_m, warp_n, g, ti, acc);
        __syncthreads();
    }

    __nv_bfloat16* Ph = g_Ph + (size_t)bh * NSEQ * NSEQ;
    __nv_bfloat16* Pl = g_Pl + (size_t)bh * NSEQ * NSEQ;
#pragma unroll
    for (int mt = 0; mt < 2; mt++) {
        int r0 = i0 + warp_m * 32 + mt * 16 + g;
#pragma unroll
        for (int nt = 0; nt < 8; nt++) {
            int col = j0 + warp_n * 64 + nt * 8 + ti * 2;
            float p0 = __expf(acc[mt][nt][0] * ATT_SCALE);
            float p1 = __expf(acc[mt][nt][1] * ATT_SCALE);
            float p2 = __expf(acc[mt][nt][2] * ATT_SCALE);
            float p3 = __expf(acc[mt][nt][3] * ATT_SCALE);
            __nv_bfloat162 hp, lp;
            split2(p0, p1, hp, lp);
            *(__nv_bfloat162*)(Ph + (size_t)r0 * NSEQ + col) = hp;
            *(__nv_bfloat162*)(Pl + (size_t)r0 * NSEQ + col) = lp;
            split2(p2, p3, hp, lp);
            *(__nv_bfloat162*)(Ph + (size_t)(r0 + 8) * NSEQ + col) = hp;
            *(__nv_bfloat162*)(Pl + (size_t)(r0 + 8) * NSEQ + col) = lp;
        }
    }
}

// =====================================================================
// colsum (deterministic): rl[bh][j] = 1 / sum_i (Ph+Pl)[i][j]
// =====================================================================
__global__ void colsum_bf() {
    const int bh = blockIdx.y;
    const int jp = blockIdx.x * 32 + threadIdx.x;     // bf162 pair index
    const int ty = threadIdx.y;                       // block (32,8)
    const size_t base = (size_t)bh * NSEQ * (NSEQ / 2) + jp;
    const __nv_bfloat162* Sh = (const __nv_bfloat162*)g_Ph + base;
    const __nv_bfloat162* Sl = (const __nv_bfloat162*)g_Pl + base;

    float s0 = 0.f, s1 = 0.f;
    for (int i = ty; i < NSEQ; i += 8) {
        __nv_bfloat162 vh = Sh[(size_t)i * (NSEQ / 2)];
        __nv_bfloat162 vl = Sl[(size_t)i * (NSEQ / 2)];
        s0 += __bfloat162float(vh.x) + __bfloat162float(vl.x);
        s1 += __bfloat162float(vh.y) + __bfloat162float(vl.y);
    }
    __shared__ float sm0[8][32], sm1[8][32];
    sm0[ty][threadIdx.x] = s0;
    sm1[ty][threadIdx.x] = s1;
    __syncthreads();
    if (ty == 0) {
#pragma unroll
        for (int r = 1; r < 8; r++) { s0 += sm0[r][threadIdx.x]; s1 += sm1[r][threadIdx.x]; }
        g_rl[bh * NSEQ + jp * 2]     = 1.0f / s0;
        g_rl[bh * NSEQ + jp * 2 + 1] = 1.0f / s1;
    }
}

// =====================================================================
// av: Y = (Ph+Pl) @ diag(rl) (Vh+Vl)   3-pass (drop Pl*Vl).
// CTA tile 128(i) x 64(d), warp tile 16 x 64, k(j) chunk 32.
// =====================================================================
__global__ __launch_bounds__(256) void av_mma() {
    __shared__ __align__(16) char sm[30720]; // Ph 10240 | Pl 10240 | Vh 5120 | Vl 5120
    char* smPh = sm;
    char* smPl = sm + 10240;
    char* smVh = sm + 20480;
    char* smVl = sm + 25600;

    const int tid = threadIdx.x, lane = tid & 31, wid = tid >> 5;
    const int g = lane >> 2, ti = lane & 3;

    const int bh = blockIdx.y;
    const int b = bh >> 4, h = bh & 15;
    const int i0 = blockIdx.x * 128;

    const size_t poff = (size_t)bh * NSEQ * NSEQ + (size_t)i0 * NSEQ;
    const __nv_bfloat16* Phg = g_Ph + poff;
    const __nv_bfloat16* Plg = g_Pl + poff;
    const float* Vbase = g_qkv + (size_t)(b * NSEQ) * QKV_COLS + 2 * HID + h * DH;
    const float* rl = g_rl + bh * NSEQ;

    const uint32_t smPhu = smem_u32(smPh);
    const uint32_t smPlu = smem_u32(smPl);
    const int jl = tid >> 3;            // 0..31  (V row)
    const int d0 = (tid & 7) * 8;       // V col group

    float acc[8][4] = {};

    for (int j0 = 0; j0 < NSEQ; j0 += 32) {
        // P hi/lo tiles via cp.async: 128 rows x 32 j each
#pragma unroll
        for (int r = 0; r < 2; r++) {
            int sid = tid + (r << 8);
            int row = sid >> 2, seg = sid & 3;
            uint32_t so = (uint32_t)(row * (LDK * 2) + seg * 16);
            size_t go = (size_t)row * NSEQ + j0 + seg * 8;
            cp_async16(smPhu + so, Phg + go);
            cp_async16(smPlu + so, Plg + go);
        }
        CP_COMMIT();
        // V tile: fp32 load, *rl, transpose + hi/lo split into smem
        {
            const float inv = rl[j0 + jl];
            const float* Vr = Vbase + (size_t)(j0 + jl) * QKV_COLS + d0;
            float4 a = *(const float4*)Vr;
            float4 c = *(const float4*)(Vr + 4);
            float vv[8] = {a.x, a.y, a.z, a.w, c.x, c.y, c.z, c.w};
#pragma unroll
            for (int e = 0; e < 8; e++) {
                float val = vv[e] * inv;
                __nv_bfloat16 hi = __float2bfloat16(val);
                __nv_bfloat16 lo = __float2bfloat16(val - __bfloat162float(hi));
                int off = ((d0 + e) * LDK + jl) * 2;
                *(__nv_bfloat16*)(smVh + off) = hi;
                *(__nv_bfloat16*)(smVl + off) = lo;
            }
        }
        cp_wait<0>();
        __syncthreads();

#pragma unroll
        for (int ks = 0; ks < 32; ks += 16) {
            uint32_t aPh[4], aPl[4];
            ldA(aPh, smPh, wid * 16, ks, g, ti);
            ldA(aPl, smPl, wid * 16, ks, g, ti);
#pragma unroll
            for (int nt = 0; nt < 8; nt++) {
                uint32_t b0, b1;
                ldB(b0, b1, smVh, nt * 8, ks, g, ti);
                mma_bf(acc[nt], aPh, b0, b1);
                mma_bf(acc[nt], aPl, b0, b1);
                ldB(b0, b1, smVl, nt * 8, ks, g, ti);
                mma_bf(acc[nt], aPh, b0, b1);
            }
        }
        __syncthreads();
    }

    // epilogue: write y hi/lo bf16
    const int irow = i0 + wid * 16 + g;
#pragma unroll
    for (int nt = 0; nt < 8; nt++) {
        int d = nt * 8 + ti * 2;
        size_t o0 = (size_t)(b * NSEQ + irow) * HID + h * DH + d;
        size_t o1 = (size_t)(b * NSEQ + irow + 8) * HID + h * DH + d;
        __nv_bfloat162 hp, lp;
        split2(acc[nt][0], acc[nt][1], hp, lp);
        *(__nv_bfloat162*)(g_yh + o0) = hp;
        *(__nv_bfloat162*)(g_yl + o0) = lp;
        split2(acc[nt][2], acc[nt][3], hp, lp);
        *(__nv_bfloat162*)(g_yh + o1) = hp;
        *(__nv_bfloat162*)(g_yl + o1) = lp;
    }
}

// =====================================================================
// split fp32 -> bf16 hi/lo (elementwise)
// =====================================================================
__global__ void split_kernel(const float* __restrict__ in,
                             __nv_bfloat16* __restrict__ hi,
                             __nv_bfloat16* __restrict__ lo, size_t n4) {
    size_t i = (size_t)blockIdx.x * blockDim.x + threadIdx.x;
    if (i >= n4) return;
    float4 v = ((const float4*)in)[i];
    __nv_bfloat162 hp0, hp1, lp0, lp1;
    split2(v.x, v.y, hp0, lp0);
    split2(v.z, v.w, hp1, lp1);
    ((__nv_bfloat162*)hi)[i * 2 + 0] = hp0;
    ((__nv_bfloat162*)hi)[i * 2 + 1] = hp1;
    ((__nv_bfloat162*)lo)[i * 2 + 0] = lp0;
    ((__nv_bfloat162*)lo)[i * 2 + 1] = lp1;
}

// =====================================================================
// transpose + split: w[K,N] fp32 -> th/tl [N,K] bf16
// =====================================================================
__global__ void transpose_split_kernel(const float* __restrict__ w,
                                       __nv_bfloat16* __restrict__ th,
                                       __nv_bfloat16* __restrict__ tl,
                                       int K, int N) {
    __shared__ float tile[32][33];
    const int k0 = blockIdx.y * 32;
    const int n0 = blockIdx.x * 32;
    const int tx = threadIdx.x, ty = threadIdx.y;   // (32,8)
#pragma unroll
    for (int r = 0; r < 4; r++)
        tile[ty + 8 * r][tx] = w[(size_t)(k0 + ty + 8 * r) * N + n0 + tx];
    __syncthreads();
#pragma unroll
    for (int r = 0; r < 4; r++) {
        const int n = n0 + ty + 8 * r;
        const int k = k0 + tx;
        float v = tile[tx][ty + 8 * r];
        __nv_bfloat16 hh = __float2bfloat16(v);
        th[(size_t)n * K + k] = hh;
        tl[(size_t)n * K + k] = __float2bfloat16(v - __bfloat162float(hh));
    }
}

// ---------------------------------------------------------------------
extern "C" void kernel_launch(void* const* d_in, const int* in_sizes, int n_in,
                              void* d_out, int out_size) {
    const float* x     = (const float*)d_in[0];
    const float* w_qkv = (const float*)d_in[1];
    const float* w_out = (const float*)d_in[2];
    const float* b_out = (const float*)d_in[3];
    float* out = (float*)d_out;

    cudaFuncSetAttribute(mma_gemm<false, true>,
                         cudaFuncAttributeMaxDynamicSharedMemorySize, DSMEM);
    cudaFuncSetAttribute(mma_gemm<true, false>,
                         cudaFuncAttributeMaxDynamicSharedMemorySize, DSMEM);
    cudaFuncSetAttribute(scores_mma,
                         cudaFuncAttributeMaxDynamicSharedMemorySize, DSMEM);

    void *p_qkv, *p_xh, *p_xl, *p_qh, *p_ql, *p_wqh, *p_wql, *p_woh, *p_wol,
         *p_yh, *p_yl;
    cudaGetSymbolAddress(&p_qkv, g_qkv);
    cudaGetSymbolAddress(&p_xh,  g_xh);
    cudaGetSymbolAddress(&p_xl,  g_xl);
    cudaGetSymbolAddress(&p_qh,  g_qkvh);
    cudaGetSymbolAddress(&p_ql,  g_qkvl);
    cudaGetSymbolAddress(&p_wqh, g_wqh);
    cudaGetSymbolAddress(&p_wql, g_wql);
    cudaGetSymbolAddress(&p_woh, g_woh);
    cudaGetSymbolAddress(&p_wol, g_wol);
    cudaGetSymbolAddress(&p_yh,  g_yh);
    cudaGetSymbolAddress(&p_yl,  g_yl);

    // 0a. split x -> bf16 hi/lo
    {
        size_t n4 = (size_t)ROWS * DIMIN / 4;
        split_kernel<<<(unsigned)((n4 + 255) / 256), 256>>>(
            x, (__nv_bfloat16*)p_xh, (__nv_bfloat16*)p_xl, n4);
    }
    // 0b/0c. transpose+split weights -> [N,K]
    transpose_split_kernel<<<dim3(QKV_COLS / 32, DIMIN / 32), dim3(32, 8)>>>(
        w_qkv, (__nv_bfloat16*)p_wqh, (__nv_bfloat16*)p_wql, DIMIN, QKV_COLS);
    transpose_split_kernel<<<dim3(HID / 32, DIMIN / 32), dim3(32, 8)>>>(
        w_out, (__nv_bfloat16*)p_woh, (__nv_bfloat16*)p_wol, DIMIN, HID);

    // 1. QKV projection (3-pass bf16 mma); writes fp32 + bf16 hi/lo
    mma_gemm<false, true><<<dim3(QKV_COLS / 128, ROWS / 128), 256, DSMEM>>>(
        (const __nv_bfloat16*)p_xh, (const __nv_bfloat16*)p_xl,
        (const __nv_bfloat16*)p_wqh, (const __nv_bfloat16*)p_wql,
        nullptr, (float*)p_qkv,
        (__nv_bfloat16*)p_qh, (__nv_bfloat16*)p_ql,
        ROWS, QKV_COLS, DIMIN);

    // 2. P = exp(scale * Q K^T)  (bf16 hi/lo)
    scores_mma<<<dim3(NSEQ / 128, NSEQ / 128, BH), 256, DSMEM>>>();

    // 3. rl = 1 / column sums (deterministic)
    colsum_bf<<<dim3(NSEQ / 64, BH), dim3(32, 8)>>>();

    // 4. Y = P diag(rl) V  -> y hi/lo bf16
    av_mma<<<dim3(NSEQ / 128, BH), 256>>>();

    // 5. out = Y @ w_out + b_out (3-pass bf16 mma)
    mma_gemm<true, false><<<dim3(HID / 128, ROWS / 128), 256, DSMEM>>>(
        (const __nv_bfloat16*)p_yh, (const __nv_bfloat16*)p_yl,
        (const __nv_bfloat16*)p_woh, (const __nv_bfloat16*)p_wol,
        b_out, out, nullptr, nullptr, ROWS, HID, DIMIN);
}

// round 6
// speedup vs baseline: 2.6723x; 1.1569x over previous
#include <cuda_runtime.h>
#include <cuda_bf16.h>
#include <math.h>
#include <stdint.h>

#define HEADS    16
#define DH       64
#define NSEQ     2048
#define BATCH    4
#define DIMIN    1024
#define HID      1024
#define ROWS     (BATCH*NSEQ)     // 8192
#define QKV_COLS (3*HID)          // 3072
#define BH       (BATCH*HEADS)    // 64
#define ATT_SCALE 0.125f
#define LDK      40               // padded k-stride (bf16 elems)
#define NITILE   (NSEQ/128)       // 16

// ---------------- static scratch ----------------
__device__ float g_qkv[(size_t)ROWS * QKV_COLS];            // fp32 (only V third written)
__device__ float g_rl[BH * NSEQ];                           // 1/colsum
__device__ float g_pcs[(size_t)BH * NITILE * NSEQ];         // partial col sums (8.4MB)
__device__ __nv_bfloat16 g_Ph [(size_t)BH * NSEQ * NSEQ];   // P hi
__device__ __nv_bfloat16 g_Pl [(size_t)BH * NSEQ * NSEQ];   // P lo
__device__ __nv_bfloat16 g_xh [(size_t)ROWS * DIMIN];
__device__ __nv_bfloat16 g_xl [(size_t)ROWS * DIMIN];
__device__ __nv_bfloat16 g_qkvh[(size_t)ROWS * QKV_COLS];   // only Q,K thirds used
__device__ __nv_bfloat16 g_qkvl[(size_t)ROWS * QKV_COLS];
__device__ __nv_bfloat16 g_wqh[(size_t)QKV_COLS * DIMIN];   // w_qkv^T hi  [N,K]
__device__ __nv_bfloat16 g_wql[(size_t)QKV_COLS * DIMIN];
__device__ __nv_bfloat16 g_woh[(size_t)DIMIN * HID];        // w_out^T hi  [N,K]
__device__ __nv_bfloat16 g_wol[(size_t)DIMIN * HID];
__device__ __nv_bfloat16 g_yh [(size_t)ROWS * HID];
__device__ __nv_bfloat16 g_yl [(size_t)ROWS * HID];

// ---------------- helpers ----------------
__device__ __forceinline__ uint32_t smem_u32(const void* p) {
    uint32_t a;
    asm("{ .reg .u64 t; cvta.to.shared.u64 t, %1; cvt.u32.u64 %0, t; }"
        : "=r"(a) : "l"(p));
    return a;
}
__device__ __forceinline__ void cp_async16(uint32_t s, const void* g) {
    asm volatile("cp.async.cg.shared.global [%0], [%1], 16;" :: "r"(s), "l"(g));
}
#define CP_COMMIT() asm volatile("cp.async.commit_group;" ::: "memory")
template <int N>
__device__ __forceinline__ void cp_wait() {
    asm volatile("cp.async.wait_group %0;" :: "n"(N) : "memory");
}
#define LDM_X4(r, a)                                                        \
    asm volatile("ldmatrix.sync.aligned.m8n8.x4.shared.b16 {%0,%1,%2,%3}, [%4];" \
        : "=r"((r)[0]), "=r"((r)[1]), "=r"((r)[2]), "=r"((r)[3]) : "r"(a))

// mma.sync m16n8k16 bf16: D += A*B  (acc fp32)
__device__ __forceinline__ void mma_bf(float* c, const uint32_t* a,
                                       uint32_t b0, uint32_t b1) {
    asm volatile(
        "mma.sync.aligned.m16n8k16.row.col.f32.bf16.bf16.f32 "
        "{%0,%1,%2,%3}, {%4,%5,%6,%7}, {%8,%9}, {%0,%1,%2,%3};\n"
        : "+f"(c[0]), "+f"(c[1]), "+f"(c[2]), "+f"(c[3])
        : "r"(a[0]), "r"(a[1]), "r"(a[2]), "r"(a[3]), "r"(b0), "r"(b1));
}

__device__ __forceinline__ void split2(float a, float b,
                                       __nv_bfloat162& hp, __nv_bfloat162& lp) {
    __nv_bfloat16 ha = __float2bfloat16(a), hb = __float2bfloat16(b);
    hp.x = ha; hp.y = hb;
    lp.x = __float2bfloat16(a - __bfloat162float(ha));
    lp.y = __float2bfloat16(b - __bfloat162float(hb));
}

// stage layout (bytes): Ah 0 | Al 10240 | Bh 20480 | Bl 30720 ; stage 40960
#define STG 40960
#define DSMEM (2*STG)

__device__ __forceinline__ void stage_load(uint32_t sbase,
    const __nv_bfloat16* Ah, const __nv_bfloat16* Al, int sA,
    const __nv_bfloat16* Bh, const __nv_bfloat16* Bl, int sB,
    int k0, int tid)
{
#pragma unroll
    for (int r = 0; r < 2; r++) {
        int sid = tid + (r << 8);
        int row = sid >> 2, seg = sid & 3;
        uint32_t so = sbase + (uint32_t)(row * (LDK * 2) + seg * 16);
        size_t oa = (size_t)row * sA + k0 + seg * 8;
        size_t ob = (size_t)row * sB + k0 + seg * 8;
        cp_async16(so,          Ah + oa);
        cp_async16(so + 10240u, Al + oa);
        cp_async16(so + 20480u, Bh + ob);
        cp_async16(so + 30720u, Bl + ob);
    }
}

// 3-pass bf16 compute of one 32-k chunk; warp tile 32(m) x 64(n); ldmatrix frags.
// ldm_off = precomputed per-lane (row_off*LDK + col_off)*2 for ldmatrix x4.
__device__ __forceinline__ void mma_chunk3(uint32_t sb, int warp_m, int warp_n,
                                           uint32_t ldm_off, float acc[2][8][4]) {
    const uint32_t bAh = sb, bAl = sb + 10240, bBh = sb + 20480, bBl = sb + 30720;
#pragma unroll
    for (int ks = 0; ks < 32; ks += 16) {
        uint32_t aH[2][4], aL[2][4];
#pragma unroll
        for (int mt = 0; mt < 2; mt++) {
            uint32_t ro = (uint32_t)((warp_m * 32 + mt * 16) * LDK + ks) * 2 + ldm_off;
            LDM_X4(aH[mt], bAh + ro);
            LDM_X4(aL[mt], bAl + ro);
        }
#pragma unroll
        for (int c = 0; c < 4; c++) {
            uint32_t bh[4], bl[4];
            uint32_t ro = (uint32_t)((warp_n * 64 + c * 16) * LDK + ks) * 2 + ldm_off;
            LDM_X4(bh, bBh + ro);
            LDM_X4(bl, bBl + ro);
#pragma unroll
            for (int half = 0; half < 2; half++) {
                int nt = c * 2 + half;
                uint32_t bh0 = bh[half], bh1 = bh[half + 2];
                uint32_t bl0 = bl[half], bl1 = bl[half + 2];
#pragma unroll
                for (int mt = 0; mt < 2; mt++) {
                    mma_bf(acc[mt][nt], aH[mt], bh0, bh1);
                    mma_bf(acc[mt][nt], aH[mt], bl0, bl1);
                    mma_bf(acc[mt][nt], aL[mt], bh0, bh1);
                }
            }
        }
    }
}

// =====================================================================
// projections: C[M,N] = (Ah+Al)[M,K] @ ((Bh+Bl)[N,K])^T
// QKV_MODE: Q/K tiles (bn<2*HID) -> write bf16 hi/lo; V tiles -> write fp32.
// =====================================================================
template <bool HAS_BIAS, bool QKV_MODE>
__global__ __launch_bounds__(256, 2) void mma_gemm(
    const __nv_bfloat16* __restrict__ Ah, const __nv_bfloat16* __restrict__ Al,
    const __nv_bfloat16* __restrict__ Bh, const __nv_bfloat16* __restrict__ Bl,
    const float* __restrict__ bias, float* __restrict__ C,
    __nv_bfloat16* __restrict__ Ch, __nv_bfloat16* __restrict__ Cl,
    int M, int N, int K)
{
    extern __shared__ char smem[];
    const uint32_t sb32 = smem_u32(smem);
    const int tid = threadIdx.x, lane = tid & 31, wid = tid >> 5;
    const int warp_m = wid & 3, warp_n = wid >> 2;
    const int g = lane >> 2, ti = lane & 3;
    const uint32_t ldm_off =
        (uint32_t)((((lane >> 3) & 1) * 8 + (lane & 7)) * LDK + ((lane >> 4) * 8)) * 2;
    const int bm = blockIdx.y * 128, bn = blockIdx.x * 128;

    const __nv_bfloat16* Ah0 = Ah + (size_t)bm * K;
    const __nv_bfloat16* Al0 = Al + (size_t)bm * K;
    const __nv_bfloat16* Bh0 = Bh + (size_t)bn * K;
    const __nv_bfloat16* Bl0 = Bl + (size_t)bn * K;

    float acc[2][8][4] = {};
    const int NT = K >> 5;

    stage_load(sb32, Ah0, Al0, K, Bh0, Bl0, K, 0, tid);
    CP_COMMIT();
    for (int kt = 0; kt < NT; kt++) {
        if (kt + 1 < NT) {
            stage_load(sb32 + ((kt + 1) & 1) * STG, Ah0, Al0, K, Bh0, Bl0, K,
                       (kt + 1) << 5, tid);
            CP_COMMIT();
            cp_wait<1>();
        } else {
            cp_wait<0>();
        }
        __syncthreads();
        mma_chunk3(sb32 + (kt & 1) * STG, warp_m, warp_n, ldm_off, acc);
        __syncthreads();
    }

    const bool isV = QKV_MODE && (bn >= 2 * HID);
#pragma unroll
    for (int mt = 0; mt < 2; mt++) {
        int r0 = bm + warp_m * 32 + mt * 16 + g;
#pragma unroll
        for (int nt = 0; nt < 8; nt++) {
            int col = bn + warp_n * 64 + nt * 8 + ti * 2;
            float v0 = acc[mt][nt][0], v1 = acc[mt][nt][1];
            float v2 = acc[mt][nt][2], v3 = acc[mt][nt][3];
            if (HAS_BIAS) {
                float2 bb = *(const float2*)(bias + col);
                v0 += bb.x; v1 += bb.y; v2 += bb.x; v3 += bb.y;
            }
            if (!QKV_MODE || isV) {
                *(float2*)(C + (size_t)r0 * N + col)       = make_float2(v0, v1);
                *(float2*)(C + (size_t)(r0 + 8) * N + col) = make_float2(v2, v3);
            }
            if (QKV_MODE && !isV) {
                __nv_bfloat162 hp, lp;
                split2(v0, v1, hp, lp);
                *(__nv_bfloat162*)(Ch + (size_t)r0 * N + col) = hp;
                *(__nv_bfloat162*)(Cl + (size_t)r0 * N + col) = lp;
                split2(v2, v3, hp, lp);
                *(__nv_bfloat162*)(Ch + (size_t)(r0 + 8) * N + col) = hp;
                *(__nv_bfloat162*)(Cl + (size_t)(r0 + 8) * N + col) = lp;
            }
        }
    }
}

// =====================================================================
// scores: P = exp(scale*q.k) -> bf16 hi/lo; also per-tile column partial sums
// =====================================================================
__global__ __launch_bounds__(256, 2) void scores_mma() {
    extern __shared__ char smem[];
    const uint32_t sb32 = smem_u32(smem);
    const int tid = threadIdx.x, lane = tid & 31, wid = tid >> 5;
    const int warp_m = wid & 3, warp_n = wid >> 2;
    const int g = lane >> 2, ti = lane & 3;
    const uint32_t ldm_off =
        (uint32_t)((((lane >> 3) & 1) * 8 + (lane & 7)) * LDK + ((lane >> 4) * 8)) * 2;

    const int bh = blockIdx.z;
    const int b = bh >> 4, h = bh & 15;
    const int i0 = blockIdx.y * 128;
    const int j0 = blockIdx.x * 128;

    const size_t qoff = (size_t)(b * NSEQ) * QKV_COLS + h * DH;
    const __nv_bfloat16* Qh = g_qkvh + qoff + (size_t)i0 * QKV_COLS;
    const __nv_bfloat16* Ql = g_qkvl + qoff + (size_t)i0 * QKV_COLS;
    const __nv_bfloat16* Kh = g_qkvh + qoff + HID + (size_t)j0 * QKV_COLS;
    const __nv_bfloat16* Kl = g_qkvl + qoff + HID + (size_t)j0 * QKV_COLS;

    float acc[2][8][4] = {};

    stage_load(sb32, Qh, Ql, QKV_COLS, Kh, Kl, QKV_COLS, 0, tid);
    CP_COMMIT();
#pragma unroll
    for (int kt = 0; kt < 2; kt++) {
        if (kt == 0) {
            stage_load(sb32 + STG, Qh, Ql, QKV_COLS, Kh, Kl, QKV_COLS, 32, tid);
            CP_COMMIT();
            cp_wait<1>();
        } else {
            cp_wait<0>();
        }
        __syncthreads();
        mma_chunk3(sb32 + kt * STG, warp_m, warp_n, ldm_off, acc);
        __syncthreads();
    }

    __nv_bfloat16* Ph = g_Ph + (size_t)bh * NSEQ * NSEQ;
    __nv_bfloat16* Pl = g_Pl + (size_t)bh * NSEQ * NSEQ;
    float cs[8][2];
#pragma unroll
    for (int nt = 0; nt < 8; nt++) { cs[nt][0] = 0.f; cs[nt][1] = 0.f; }

#pragma unroll
    for (int mt = 0; mt < 2; mt++) {
        int r0 = i0 + warp_m * 32 + mt * 16 + g;
#pragma unroll
        for (int nt = 0; nt < 8; nt++) {
            int col = j0 + warp_n * 64 + nt * 8 + ti * 2;
            float p0 = __expf(acc[mt][nt][0] * ATT_SCALE);
            float p1 = __expf(acc[mt][nt][1] * ATT_SCALE);
            float p2 = __expf(acc[mt][nt][2] * ATT_SCALE);
            float p3 = __expf(acc[mt][nt][3] * ATT_SCALE);
            cs[nt][0] += p0 + p2;
            cs[nt][1] += p1 + p3;
            __nv_bfloat162 hp, lp;
            split2(p0, p1, hp, lp);
            *(__nv_bfloat162*)(Ph + (size_t)r0 * NSEQ + col) = hp;
            *(__nv_bfloat162*)(Pl + (size_t)r0 * NSEQ + col) = lp;
            split2(p2, p3, hp, lp);
            *(__nv_bfloat162*)(Ph + (size_t)(r0 + 8) * NSEQ + col) = hp;
            *(__nv_bfloat162*)(Pl + (size_t)(r0 + 8) * NSEQ + col) = lp;
        }
    }

    // butterfly over g-lanes (bits 2..4 of lane) -> column sums over warp's 32 rows
#pragma unroll
    for (int nt = 0; nt < 8; nt++) {
#pragma unroll
        for (int e = 0; e < 2; e++) {
            float v = cs[nt][e];
            v += __shfl_xor_sync(0xFFFFFFFF, v, 4);
            v += __shfl_xor_sync(0xFFFFFFFF, v, 8);
            v += __shfl_xor_sync(0xFFFFFFFF, v, 16);
            cs[nt][e] = v;
        }
    }
    float* spart = (float*)smem;          // [4][128], stage smem is free now
    if (g == 0) {
#pragma unroll
        for (int nt = 0; nt < 8; nt++) {
            spart[warp_m * 128 + warp_n * 64 + nt * 8 + ti * 2]     = cs[nt][0];
            spart[warp_m * 128 + warp_n * 64 + nt * 8 + ti * 2 + 1] = cs[nt][1];
        }
    }
    __syncthreads();
    if (tid < 128) {
        float s = spart[tid] + spart[128 + tid] + spart[256 + tid] + spart[384 + tid];
        g_pcs[((size_t)bh * NITILE + blockIdx.y) * NSEQ + j0 + tid] = s;
    }
}

// =====================================================================
// rsum: rl[bh][j] = 1 / sum_itile pcs
// =====================================================================
__global__ void rsum_kernel() {
    const int bh = blockIdx.y;
    const int j = blockIdx.x * 256 + threadIdx.x;
    const float* p = g_pcs + (size_t)bh * NITILE * NSEQ + j;
    float s = 0.f;
#pragma unroll
    for (int t = 0; t < NITILE; t++) s += p[(size_t)t * NSEQ];
    g_rl[bh * NSEQ + j] = 1.0f / s;
}

// =====================================================================
// av: Y = (Ph+Pl) @ diag(rl) (Vh+Vl)   3-pass (drop Pl*Vl).
// CTA tile 128(i) x 64(d), warp tile 16 x 64, k(j) chunk 32.
// =====================================================================
__global__ __launch_bounds__(256) void av_mma() {
    __shared__ __align__(16) char sm[30720]; // Ph 10240 | Pl 10240 | Vh 5120 | Vl 5120
    const uint32_t smPh = smem_u32(sm);
    const uint32_t smPl = smPh + 10240;
    const uint32_t smVh = smPh + 20480;
    const uint32_t smVl = smPh + 25600;
    char* smVhc = sm + 20480;
    char* smVlc = sm + 25600;

    const int tid = threadIdx.x, lane = tid & 31, wid = tid >> 5;
    const int g = lane >> 2, ti = lane & 3;
    const uint32_t ldm_off =
        (uint32_t)((((lane >> 3) & 1) * 8 + (lane & 7)) * LDK + ((lane >> 4) * 8)) * 2;

    const int bh = blockIdx.y;
    const int b = bh >> 4, h = bh & 15;
    const int i0 = blockIdx.x * 128;

    const size_t poff = (size_t)bh * NSEQ * NSEQ + (size_t)i0 * NSEQ;
    const __nv_bfloat16* Phg = g_Ph + poff;
    const __nv_bfloat16* Plg = g_Pl + poff;
    const float* Vbase = g_qkv + (size_t)(b * NSEQ) * QKV_COLS + 2 * HID + h * DH;
    const float* rl = g_rl + bh * NSEQ;

    const int jl = tid >> 3;            // 0..31  (V row)
    const int d0 = (tid & 7) * 8;       // V col group

    float acc[8][4] = {};

    for (int j0 = 0; j0 < NSEQ; j0 += 32) {
        // P hi/lo tiles via cp.async: 128 rows x 32 j each
#pragma unroll
        for (int r = 0; r < 2; r++) {
            int sid = tid + (r << 8);
            int row = sid >> 2, seg = sid & 3;
            uint32_t so = (uint32_t)(row * (LDK * 2) + seg * 16);
            size_t go = (size_t)row * NSEQ + j0 + seg * 8;
            cp_async16(smPh + so, Phg + go);
            cp_async16(smPl + so, Plg + go);
        }
        CP_COMMIT();
        // V tile: fp32 load, *rl, transpose + hi/lo split into smem
        {
            const float inv = rl[j0 + jl];
            const float* Vr = Vbase + (size_t)(j0 + jl) * QKV_COLS + d0;
            float4 a = *(const float4*)Vr;
            float4 c = *(const float4*)(Vr + 4);
            float vv[8] = {a.x, a.y, a.z, a.w, c.x, c.y, c.z, c.w};
#pragma unroll
            for (int e = 0; e < 8; e++) {
                float val = vv[e] * inv;
                __nv_bfloat16 hi = __float2bfloat16(val);
                __nv_bfloat16 lo = __float2bfloat16(val - __bfloat162float(hi));
                int off = ((d0 + e) * LDK + jl) * 2;
                *(__nv_bfloat16*)(smVhc + off) = hi;
                *(__nv_bfloat16*)(smVlc + off) = lo;
            }
        }
        cp_wait<0>();
        __syncthreads();

#pragma unroll
        for (int ks = 0; ks < 32; ks += 16) {
            uint32_t aPh[4], aPl[4];
            uint32_t ro = (uint32_t)((wid * 16) * LDK + ks) * 2 + ldm_off;
            LDM_X4(aPh, smPh + ro);
            LDM_X4(aPl, smPl + ro);
#pragma unroll
            for (int c = 0; c < 4; c++) {
                uint32_t bhm[4], blm[4];
                uint32_t rb = (uint32_t)((c * 16) * LDK + ks) * 2 + ldm_off;
                LDM_X4(bhm, smVh + rb);
                LDM_X4(blm, smVl + rb);
#pragma unroll
                for (int half = 0; half < 2; half++) {
                    int nt = c * 2 + half;
                    mma_bf(acc[nt], aPh, bhm[half], bhm[half + 2]);
                    mma_bf(acc[nt], aPl, bhm[half], bhm[half + 2]);
                    mma_bf(acc[nt], aPh, blm[half], blm[half + 2]);
                }
            }
        }
        __syncthreads();
    }

    // epilogue: write y hi/lo bf16
    const int irow = i0 + wid * 16 + g;
#pragma unroll
    for (int nt = 0; nt < 8; nt++) {
        int d = nt * 8 + ti * 2;
        size_t o0 = (size_t)(b * NSEQ + irow) * HID + h * DH + d;
        size_t o1 = (size_t)(b * NSEQ + irow + 8) * HID + h * DH + d;
        __nv_bfloat162 hp, lp;
        split2(acc[nt][0], acc[nt][1], hp, lp);
        *(__nv_bfloat162*)(g_yh + o0) = hp;
        *(__nv_bfloat162*)(g_yl + o0) = lp;
        split2(acc[nt][2], acc[nt][3], hp, lp);
        *(__nv_bfloat162*)(g_yh + o1) = hp;
        *(__nv_bfloat162*)(g_yl + o1) = lp;
    }
}

// =====================================================================
// split fp32 -> bf16 hi/lo (elementwise)
// =====================================================================
__global__ void split_kernel(const float* __restrict__ in,
                             __nv_bfloat16* __restrict__ hi,
                             __nv_bfloat16* __restrict__ lo, size_t n4) {
    size_t i = (size_t)blockIdx.x * blockDim.x + threadIdx.x;
    if (i >= n4) return;
    float4 v = ((const float4*)in)[i];
    __nv_bfloat162 hp0, hp1, lp0, lp1;
    split2(v.x, v.y, hp0, lp0);
    split2(v.z, v.w, hp1, lp1);
    ((__nv_bfloat162*)hi)[i * 2 + 0] = hp0;
    ((__nv_bfloat162*)hi)[i * 2 + 1] = hp1;
    ((__nv_bfloat162*)lo)[i * 2 + 0] = lp0;
    ((__nv_bfloat162*)lo)[i * 2 + 1] = lp1;
}

// =====================================================================
// transpose + split: w[K,N] fp32 -> th/tl [N,K] bf16
// =====================================================================
__global__ void transpose_split_kernel(const float* __restrict__ w,
                                       __nv_bfloat16* __restrict__ th,
                                       __nv_bfloat16* __restrict__ tl,
                                       int K, int N) {
    __shared__ float tile[32][33];
    const int k0 = blockIdx.y * 32;
    const int n0 = blockIdx.x * 32;
    const int tx = threadIdx.x, ty = threadIdx.y;   // (32,8)
#pragma unroll
    for (int r = 0; r < 4; r++)
        tile[ty + 8 * r][tx] = w[(size_t)(k0 + ty + 8 * r) * N + n0 + tx];
    __syncthreads();
#pragma unroll
    for (int r = 0; r < 4; r++) {
        const int n = n0 + ty + 8 * r;
        const int k = k0 + tx;
        float v = tile[tx][ty + 8 * r];
        __nv_bfloat16 hh = __float2bfloat16(v);
        th[(size_t)n * K + k] = hh;
        tl[(size_t)n * K + k] = __float2bfloat16(v - __bfloat162float(hh));
    }
}

// ---------------------------------------------------------------------
extern "C" void kernel_launch(void* const* d_in, const int* in_sizes, int n_in,
                              void* d_out, int out_size) {
    const float* x     = (const float*)d_in[0];
    const float* w_qkv = (const float*)d_in[1];
    const float* w_out = (const float*)d_in[2];
    const float* b_out = (const float*)d_in[3];
    float* out = (float*)d_out;

    cudaFuncSetAttribute(mma_gemm<false, true>,
                         cudaFuncAttributeMaxDynamicSharedMemorySize, DSMEM);
    cudaFuncSetAttribute(mma_gemm<true, false>,
                         cudaFuncAttributeMaxDynamicSharedMemorySize, DSMEM);
    cudaFuncSetAttribute(scores_mma,
                         cudaFuncAttributeMaxDynamicSharedMemorySize, DSMEM);

    void *p_qkv, *p_xh, *p_xl, *p_qh, *p_ql, *p_wqh, *p_wql, *p_woh, *p_wol,
         *p_yh, *p_yl;
    cudaGetSymbolAddress(&p_qkv, g_qkv);
    cudaGetSymbolAddress(&p_xh,  g_xh);
    cudaGetSymbolAddress(&p_xl,  g_xl);
    cudaGetSymbolAddress(&p_qh,  g_qkvh);
    cudaGetSymbolAddress(&p_ql,  g_qkvl);
    cudaGetSymbolAddress(&p_wqh, g_wqh);
    cudaGetSymbolAddress(&p_wql, g_wql);
    cudaGetSymbolAddress(&p_woh, g_woh);
    cudaGetSymbolAddress(&p_wol, g_wol);
    cudaGetSymbolAddress(&p_yh,  g_yh);
    cudaGetSymbolAddress(&p_yl,  g_yl);

    // 0a. split x -> bf16 hi/lo
    {
        size_t n4 = (size_t)ROWS * DIMIN / 4;
        split_kernel<<<(unsigned)((n4 + 255) / 256), 256>>>(
            x, (__nv_bfloat16*)p_xh, (__nv_bfloat16*)p_xl, n4);
    }
    // 0b/0c. transpose+split weights -> [N,K]
    transpose_split_kernel<<<dim3(QKV_COLS / 32, DIMIN / 32), dim3(32, 8)>>>(
        w_qkv, (__nv_bfloat16*)p_wqh, (__nv_bfloat16*)p_wql, DIMIN, QKV_COLS);
    transpose_split_kernel<<<dim3(HID / 32, DIMIN / 32), dim3(32, 8)>>>(
        w_out, (__nv_bfloat16*)p_woh, (__nv_bfloat16*)p_wol, DIMIN, HID);

    // 1. QKV projection: Q/K -> bf16 hi/lo, V -> fp32
    mma_gemm<false, true><<<dim3(QKV_COLS / 128, ROWS / 128), 256, DSMEM>>>(
        (const __nv_bfloat16*)p_xh, (const __nv_bfloat16*)p_xl,
        (const __nv_bfloat16*)p_wqh, (const __nv_bfloat16*)p_wql,
        nullptr, (float*)p_qkv,
        (__nv_bfloat16*)p_qh, (__nv_bfloat16*)p_ql,
        ROWS, QKV_COLS, DIMIN);

    // 2. P = exp(scale * Q K^T) (bf16 hi/lo) + partial column sums
    scores_mma<<<dim3(NSEQ / 128, NSEQ / 128, BH), 256, DSMEM>>>();

    // 3. rl = 1 / column sums (from partials)
    rsum_kernel<<<dim3(NSEQ / 256, BH), 256>>>();

    // 4. Y = P diag(rl) V  -> y hi/lo bf16
    av_mma<<<dim3(NSEQ / 128, BH), 256>>>();

    // 5. out = Y @ w_out + b_out
    mma_gemm<true, false><<<dim3(HID / 128, ROWS / 128), 256, DSMEM>>>(
        (const __nv_bfloat16*)p_yh, (const __nv_bfloat16*)p_yl,
        (const __nv_bfloat16*)p_woh, (const __nv_bfloat16*)p_wol,
        b_out, out, nullptr, nullptr, ROWS, HID, DIMIN);
}